// round 14
// baseline (speedup 1.0000x reference)
#include <cuda_runtime.h>
#include <cuda_fp16.h>
#include <cstdint>

#define BATCH 4
#define CKD   64
#define CVD   512
#define NMEM  9216
#define MQ    2304
#define NT    128
#define NTILES 72
#define THREADS 512

#define SQK 72            // Qh/Kh row stride (halfs): conflict-free fragments
#define SPV 136           // Ph/Vh row stride (halfs)

// smem layout (float offsets)
#define OQH  0            // Qh [128 m][72] f16          4608 f
#define OKH  4608         // Kh [128 n][72] f16          4608 f
#define OPH0 9216         // Ph buf0 [128 m][136] f16    8704 f
#define OPH1 17920        // Ph buf1                     8704 f
#define OVH  26624        // Vh [128 cv][136] f16        8704 f
#define ORA  35328        // row-sum partials [2][128]
#define OINV 35584        // inv row sums [128]
#define SM_FLOATS 35712
#define SMEM_BYTES (SM_FLOATS * 4)   // 142,848 B

// barrier ids: 1,2 = Ph full[buf]; 3,4 = Ph empty[buf]; 5 = G1; 6 = G2; 7 = final
#define BARS(id, cnt) asm volatile("bar.sync %0, %1;"   :: "r"(id), "r"(cnt) : "memory")
#define BARA(id, cnt) asm volatile("bar.arrive %0, %1;" :: "r"(id), "r"(cnt) : "memory")

__device__ __forceinline__ uint32_t h2u(__half2 h) { return *(uint32_t*)&h; }

__device__ __forceinline__ void mma16(float c[4], const uint32_t a[4],
                                      uint32_t b0, uint32_t b1) {
    asm volatile(
        "mma.sync.aligned.m16n8k16.row.col.f32.f16.f16.f32 "
        "{%0,%1,%2,%3}, {%4,%5,%6,%7}, {%8,%9}, {%0,%1,%2,%3};"
        : "+f"(c[0]), "+f"(c[1]), "+f"(c[2]), "+f"(c[3])
        : "r"(a[0]), "r"(a[1]), "r"(a[2]), "r"(a[3]), "r"(b0), "r"(b1));
}

// ---------------------------------------------------------------------------
__global__ __launch_bounds__(THREADS, 1)
void mr_kernel(const float* __restrict__ mk, const float* __restrict__ qk,
               const float* __restrict__ mv, float* __restrict__ out) {
    extern __shared__ float sm[];
    __half* Qh = (__half*)(sm + OQH);
    __half* Kh = (__half*)(sm + OKH);
    __half* Vh = (__half*)(sm + OVH);

    const int t = threadIdx.x, lane = t & 31;
    const int g = lane >> 2, tig = lane & 3;
    const int b = blockIdx.z;
    const int m0 = blockIdx.x * 128, cv0 = blockIdx.y * 128;

    const float* qb = qk + (size_t)b * CKD * MQ + m0;
    const float* kb = mk + (size_t)b * CKD * NMEM;
    const float* vb = mv + ((size_t)b * CVD + cv0) * NMEM;

    // ---- prologue (all 512): Q -> Qh[m][c] f16 (LDG transpose), once ----
    {
        const int mq_ = t & 127, cq = t >> 7;        // 4 c-groups of 16
        const float* qt = qb + mq_;
#pragma unroll 4
        for (int i = 0; i < 8; i++) {
            int c0 = cq * 16 + 2 * i;
            float x0 = qt[(size_t)c0 * MQ];
            float x1 = qt[(size_t)(c0 + 1) * MQ];
            *(__half2*)&Qh[mq_ * SQK + c0] = __floats2half2_rn(x0, x1);
        }
    }
    __syncthreads();

    if (t < 256) {
        // ================= G1: K convert + GEMM1 + epilogue =================
        const int w1 = t >> 5, wm1 = w1 & 3, wn1 = w1 >> 2;  // 4(m) x 2(n)
        const int nk = t & 127, ch = t >> 7;                 // K convert map
        const int mb = wm1 * 32, nb = wn1 * 64;
        float rsum[4] = {0.f, 0.f, 0.f, 0.f};

        for (int tt = 0; tt < NTILES; tt++) {
            const int buf = tt & 1;
            if (tt >= 2) BARS(3 + buf, 512);     // Ph[buf] consumed (tt-2)
            BARS(5, 256);                        // all G1 done reading Kh

            // K convert: gmem [64c][128n] -> Kh[n][c] f16
            {
                const float* kt = kb + (size_t)tt * NT + nk;
#pragma unroll 4
                for (int i = 0; i < 16; i++) {
                    int c0 = ch * 32 + 2 * i;
                    float x0 = kt[(size_t)c0 * NMEM];
                    float x1 = kt[(size_t)(c0 + 1) * NMEM];
                    *(__half2*)&Kh[nk * SQK + c0] = __floats2half2_rn(x0, x1);
                }
            }
            BARS(5, 256);                        // Kh ready

            // GEMM1: S[32m x 64n] per warp, K=64
            float sacc[2][8][4] = {};
#pragma unroll
            for (int j = 0; j < 4; j++) {
                const int col = 16 * j + 2 * tig;
                uint32_t a[2][4];
#pragma unroll
                for (int i = 0; i < 2; i++) {
                    int r = mb + 16 * i + g;
                    a[i][0] = *(uint32_t*)&Qh[r * SQK + col];
                    a[i][1] = *(uint32_t*)&Qh[(r + 8) * SQK + col];
                    a[i][2] = *(uint32_t*)&Qh[r * SQK + col + 8];
                    a[i][3] = *(uint32_t*)&Qh[(r + 8) * SQK + col + 8];
                }
#pragma unroll
                for (int f = 0; f < 8; f++) {
                    int nr = nb + 8 * f + g;
                    uint32_t b0 = *(uint32_t*)&Kh[nr * SQK + col];
                    uint32_t b1 = *(uint32_t*)&Kh[nr * SQK + col + 8];
                    mma16(sacc[0][f], a[0], b0, b1);
                    mma16(sacc[1][f], a[1], b0, b1);
                }
            }

            // epilogue: exp -> Ph[buf], row-sum partials
            {
                __half* PhB = (__half*)(sm + (buf ? OPH1 : OPH0));
                float ps[4] = {0.f, 0.f, 0.f, 0.f};
#pragma unroll
                for (int i = 0; i < 2; i++)
#pragma unroll
                    for (int f = 0; f < 8; f++) {
                        float e0 = __expf(sacc[i][f][0] * 0.125f);
                        float e1 = __expf(sacc[i][f][1] * 0.125f);
                        float e2 = __expf(sacc[i][f][2] * 0.125f);
                        float e3 = __expf(sacc[i][f][3] * 0.125f);
                        ps[2 * i]     += e0 + e1;
                        ps[2 * i + 1] += e2 + e3;
                        int col = nb + 8 * f + 2 * tig;
                        int r = mb + 16 * i + g;
                        *(__half2*)&PhB[r * SPV + col] = __floats2half2_rn(e0, e1);
                        *(__half2*)&PhB[(r + 8) * SPV + col] = __floats2half2_rn(e2, e3);
                    }
#pragma unroll
                for (int q = 0; q < 4; q++) {
                    ps[q] += __shfl_xor_sync(0xffffffffu, ps[q], 1);
                    ps[q] += __shfl_xor_sync(0xffffffffu, ps[q], 2);
                    rsum[q] += ps[q];
                }
            }
            BARA(1 + buf, 512);                  // Ph[buf] full
        }

        // row-sum partials -> ORA, then OINV, then signal G2
        if (tig == 0) {
            float* rs = sm + ORA + wn1 * 128;
            rs[mb + g]      = rsum[0];
            rs[mb + g + 8]  = rsum[1];
            rs[mb + g + 16] = rsum[2];
            rs[mb + g + 24] = rsum[3];
        }
        BARS(5, 256);
        if (t < 128)
            sm[OINV + t] = 1.0f / (sm[ORA + t] + sm[ORA + 128 + t]);
        BARA(7, 512);
    } else {
        // ================= G2: V convert + GEMM2 + store =================
        const int tl = t - 256;
        const int w2 = tl >> 5, wc = w2 & 3, wm2 = w2 >> 2;  // 4(cv) x 2(m)
        const int cb = wc * 32, mb2 = wm2 * 64;
        float oacc[2][8][4] = {};

        for (int tt = 0; tt < NTILES; tt++) {
            const int buf = tt & 1;
            BARS(6, 256);                        // all G2 done reading Vh

            // V convert: gmem [128cv][128n] -> Vh f16
            {
#pragma unroll 4
                for (int i = 0; i < 16; i++) {
                    int idx = tl + 256 * i, cv = idx >> 5, q4 = (idx & 31) * 4;
                    float4 x = *(const float4*)&vb[(size_t)cv * NMEM + tt * NT + q4];
                    __half2 h0 = __floats2half2_rn(x.x, x.y);
                    __half2 h1 = __floats2half2_rn(x.z, x.w);
                    *(uint2*)&Vh[cv * SPV + q4] = make_uint2(h2u(h0), h2u(h1));
                }
            }
            BARS(6, 256);                        // Vh ready
            BARS(1 + buf, 512);                  // Ph[buf] full

            // GEMM2: O^T[32cv x 64m] per warp, K=128
            const __half* PhB = (const __half*)(sm + (buf ? OPH1 : OPH0));
#pragma unroll
            for (int u = 0; u < 8; u++) {
                const int col = 16 * u + 2 * tig;
                uint32_t a[2][4];
#pragma unroll
                for (int i = 0; i < 2; i++) {
                    int r = cb + 16 * i + g;
                    a[i][0] = *(uint32_t*)&Vh[r * SPV + col];
                    a[i][1] = *(uint32_t*)&Vh[(r + 8) * SPV + col];
                    a[i][2] = *(uint32_t*)&Vh[r * SPV + col + 8];
                    a[i][3] = *(uint32_t*)&Vh[(r + 8) * SPV + col + 8];
                }
#pragma unroll
                for (int f = 0; f < 8; f++) {
                    int mr = mb2 + 8 * f + g;
                    uint32_t b0 = *(uint32_t*)&PhB[mr * SPV + col];
                    uint32_t b1 = *(uint32_t*)&PhB[mr * SPV + col + 8];
                    mma16(oacc[0][f], a[0], b0, b1);
                    mma16(oacc[1][f], a[1], b0, b1);
                }
            }
            BARA(3 + buf, 512);                  // Ph[buf] empty
        }

        BARS(7, 512);                            // OINV ready
#pragma unroll
        for (int i = 0; i < 2; i++)
#pragma unroll
            for (int f = 0; f < 8; f++) {
                int m_ = mb2 + 8 * f + 2 * tig;
                float iv0 = sm[OINV + m_], iv1 = sm[OINV + m_ + 1];
                int cv = cb + 16 * i + g;
                float* o0 = out + ((size_t)b * CVD + cv0 + cv) * MQ + m0 + m_;
                float* o1 = o0 + (size_t)8 * MQ;
                *(float2*)o0 = make_float2(oacc[i][f][0] * iv0, oacc[i][f][1] * iv1);
                *(float2*)o1 = make_float2(oacc[i][f][2] * iv0, oacc[i][f][3] * iv1);
            }
    }
}

// ---------------------------------------------------------------------------
extern "C" void kernel_launch(void* const* d_in, const int* in_sizes, int n_in,
                              void* d_out, int out_size) {
    const float* mk = (const float*)d_in[0];
    const float* qk = (const float*)d_in[1];
    const float* mv = (const float*)d_in[2];
    float* out = (float*)d_out;

    cudaFuncSetAttribute(mr_kernel, cudaFuncAttributeMaxDynamicSharedMemorySize,
                         SMEM_BYTES);
    dim3 grid(MQ / 128, CVD / 128, BATCH);   // 18 x 4 x 4 = 288
    mr_kernel<<<grid, THREADS, SMEM_BYTES>>>(mk, qk, mv, out);
}

// round 15
// speedup vs baseline: 1.3000x; 1.3000x over previous
#include <cuda_runtime.h>
#include <cuda_fp16.h>
#include <cstdint>

#define BATCH 4
#define CKD   64
#define CVD   512
#define NMEM  9216
#define MQ    2304
#define NT    128
#define NTILES 72
#define THREADS 512

#define SQK 72            // Qh/Kh row stride (halfs); 144B ≡ 16 mod 128 -> LDSM conflict-free
#define SPV 136           // Ph/Vh row stride (halfs); 272B ≡ 16 mod 128

// smem layout (float offsets)
#define OQH  0            // Qh  [128 m][72]  f16      4608 f
#define OKH0 4608         // Kh buf0 [128 n][72] f16   4608 f
#define OKH1 9216         // Kh buf1                   4608 f
#define OPH  13824        // Ph [128 m][136] f16       8704 f
#define OVH  22528        // Vh [128 cv][136] f16      8704 f
#define ORA  31232        // row-sum partials [4][128]
#define OINV 31744
#define SM_FLOATS 31872
#define SMEM_BYTES (SM_FLOATS * 4)   // 127,488 B

#define QSCALE (0.125f * 1.4426950408889634f)   // fold 1/sqrt(64) and log2(e) into Q

// ---------------------------------------------------------------------------
__device__ __forceinline__ uint32_t s2u(const void* p) {
    uint32_t a;
    asm("{.reg .u64 t; cvta.to.shared.u64 t, %1; cvt.u32.u64 %0, t;}" : "=r"(a) : "l"(p));
    return a;
}
__device__ __forceinline__ uint32_t h2u(__half2 h) { return *(uint32_t*)&h; }
__device__ __forceinline__ float ex2f(float x) {
    float y; asm("ex2.approx.ftz.f32 %0, %1;" : "=f"(y) : "f"(x)); return y;
}
__device__ __forceinline__ void ldsm_x4(uint32_t r[4], uint32_t addr) {
    asm volatile("ldmatrix.sync.aligned.m8n8.x4.shared.b16 {%0,%1,%2,%3}, [%4];"
        : "=r"(r[0]), "=r"(r[1]), "=r"(r[2]), "=r"(r[3]) : "r"(addr));
}
__device__ __forceinline__ void mma16(float c[4], const uint32_t a[4],
                                      uint32_t b0, uint32_t b1) {
    asm volatile(
        "mma.sync.aligned.m16n8k16.row.col.f32.f16.f16.f32 "
        "{%0,%1,%2,%3}, {%4,%5,%6,%7}, {%8,%9}, {%0,%1,%2,%3};"
        : "+f"(c[0]), "+f"(c[1]), "+f"(c[2]), "+f"(c[3])
        : "r"(a[0]), "r"(a[1]), "r"(a[2]), "r"(a[3]), "r"(b0), "r"(b1));
}

// ---------------------------------------------------------------------------
__global__ __launch_bounds__(THREADS, 1)
void mr_kernel(const float* __restrict__ mk, const float* __restrict__ qk,
               const float* __restrict__ mv, float* __restrict__ out) {
    extern __shared__ float sm[];
    __half* Qh = (__half*)(sm + OQH);
    __half* Ph = (__half*)(sm + OPH);
    __half* Vh = (__half*)(sm + OVH);
    const uint32_t QhU = s2u(Qh), PhU = s2u(Ph), VhU = s2u(Vh);

    const int t = threadIdx.x, lane = t & 31, wid = t >> 5;
    const int g = lane >> 2, tig = lane & 3;
    const int wm = wid & 3, wn = wid >> 2;          // 4 x 4 warp grid
    const int b = blockIdx.z;
    const int m0 = blockIdx.x * 128, cv0 = blockIdx.y * 128;

    const float* qb = qk + (size_t)b * CKD * MQ + m0;
    const float* kb = mk + (size_t)b * CKD * NMEM;
    const float* vb = mv + ((size_t)b * CVD + cv0) * NMEM;

    const int nk = t & 127, chg = t >> 7;           // convert maps (coalesced)

    // ---- prologue: Q (scaled) and K_0, direct LDG-transpose converts ----
    {
        const float* qt = qb + nk;
#pragma unroll 4
        for (int i = 0; i < 8; i++) {
            int c0 = chg * 16 + 2 * i;
            float x0 = qt[(size_t)c0 * MQ] * QSCALE;
            float x1 = qt[(size_t)(c0 + 1) * MQ] * QSCALE;
            *(__half2*)&Qh[nk * SQK + c0] = __floats2half2_rn(x0, x1);
        }
        __half* Kh0 = (__half*)(sm + OKH0);
        const float* kt = kb + nk;
#pragma unroll 4
        for (int i = 0; i < 8; i++) {
            int c0 = chg * 16 + 2 * i;
            float x0 = kt[(size_t)c0 * NMEM];
            float x1 = kt[(size_t)(c0 + 1) * NMEM];
            *(__half2*)&Kh0[nk * SQK + c0] = __floats2half2_rn(x0, x1);
        }
    }

    const int lrow = lane & 15, lcol = (lane >> 4) * 8;   // LDSM lane mapping
    float oacc[2][4][4] = {};
    float rsum[4] = {0.f, 0.f, 0.f, 0.f};

    for (int tt = 0; tt < NTILES; tt++) {
        const int n0 = tt * NT;
        const uint32_t KhCU = s2u(sm + ((tt & 1) ? OKH1 : OKH0));
        __half* KhN = (__half*)(sm + ((tt & 1) ? OKH0 : OKH1));
        const bool hasN1 = (tt + 1 < NTILES);

        __syncthreads();   // prev GEMM2 done: Vh/Ph free, KhC(KhN of prev) ready

        // ---- GEMM1 (Qh·KhC^T) interleaved with V LDG->f16->Vh ----
        float sacc[2][4][4] = {};
        {
            const int mb = wm * 32, nb = wn * 32;
            const uint32_t aA = QhU + 2 * ((mb + lrow) * SQK + lcol);
            const uint32_t aB = KhCU + 2 * ((nb + lrow) * SQK + lcol);
#pragma unroll
            for (int j = 0; j < 4; j++) {
                // V chunk loads (coalesced float4) — issue early
                int idx0 = t + THREADS * (2 * j), idx1 = idx0 + THREADS;
                float4 v0 = *(const float4*)&vb[(size_t)(idx0 >> 5) * NMEM + n0 + (idx0 & 31) * 4];
                float4 v1 = *(const float4*)&vb[(size_t)(idx1 >> 5) * NMEM + n0 + (idx1 & 31) * 4];

                uint32_t A0[4], A1[4], B0[4], B1[4];
                ldsm_x4(A0, aA + 32 * j);
                ldsm_x4(A1, aA + 32 * j + 32 * SQK);
                ldsm_x4(B0, aB + 32 * j);
                ldsm_x4(B1, aB + 32 * j + 32 * SQK);
                mma16(sacc[0][0], A0, B0[0], B0[2]);
                mma16(sacc[1][0], A1, B0[0], B0[2]);
                mma16(sacc[0][1], A0, B0[1], B0[3]);
                mma16(sacc[1][1], A1, B0[1], B0[3]);
                mma16(sacc[0][2], A0, B1[0], B1[2]);
                mma16(sacc[1][2], A1, B1[0], B1[2]);
                mma16(sacc[0][3], A0, B1[1], B1[3]);
                mma16(sacc[1][3], A1, B1[1], B1[3]);

                __half2 h00 = __floats2half2_rn(v0.x, v0.y);
                __half2 h01 = __floats2half2_rn(v0.z, v0.w);
                *(uint2*)&Vh[(idx0 >> 5) * SPV + (idx0 & 31) * 4] =
                    make_uint2(h2u(h00), h2u(h01));
                __half2 h10 = __floats2half2_rn(v1.x, v1.y);
                __half2 h11 = __floats2half2_rn(v1.z, v1.w);
                *(uint2*)&Vh[(idx1 >> 5) * SPV + (idx1 & 31) * 4] =
                    make_uint2(h2u(h10), h2u(h11));
            }
        }

        // ---- epilogue: exp2 -> Ph (f16), per-row partial sums ----
        {
            const int mb = wm * 32, nb = wn * 32;
            float ps[4] = {0.f, 0.f, 0.f, 0.f};
#pragma unroll
            for (int i = 0; i < 2; i++)
#pragma unroll
                for (int f = 0; f < 4; f++) {
                    float e0 = ex2f(sacc[i][f][0]);
                    float e1 = ex2f(sacc[i][f][1]);
                    float e2 = ex2f(sacc[i][f][2]);
                    float e3 = ex2f(sacc[i][f][3]);
                    ps[2 * i]     += e0 + e1;
                    ps[2 * i + 1] += e2 + e3;
                    int col = nb + 8 * f + 2 * tig;
                    int r = mb + 16 * i + g;
                    *(__half2*)&Ph[r * SPV + col] = __floats2half2_rn(e0, e1);
                    *(__half2*)&Ph[(r + 8) * SPV + col] = __floats2half2_rn(e2, e3);
                }
#pragma unroll
            for (int q = 0; q < 4; q++) {
                ps[q] += __shfl_xor_sync(0xffffffffu, ps[q], 1);
                ps[q] += __shfl_xor_sync(0xffffffffu, ps[q], 2);
                rsum[q] += ps[q];
            }
        }
        __syncthreads();           // Ph + Vh visible

        // ---- GEMM2 (Vh·Ph^T) interleaved with K-convert(tt+1) ----
        {
            const int cb = wm * 32, mb2 = wn * 32;
            const uint32_t aV = VhU + 2 * ((cb + lrow) * SPV + lcol);
            const uint32_t aP = PhU + 2 * ((mb2 + lrow) * SPV + lcol);
            const float* kt = kb + (size_t)(tt + 1) * NT + nk;

            float kx0 = 0.f, kx1 = 0.f;
            if (hasN1) {
                kx0 = kt[(size_t)(chg * 16) * NMEM];
                kx1 = kt[(size_t)(chg * 16 + 1) * NMEM];
            }
#pragma unroll
            for (int u = 0; u < 8; u++) {
                float nx0 = 0.f, nx1 = 0.f;
                if (hasN1 && u < 7) {     // issue next chunk's LDGs early
                    nx0 = kt[(size_t)(chg * 16 + 2 * u + 2) * NMEM];
                    nx1 = kt[(size_t)(chg * 16 + 2 * u + 3) * NMEM];
                }
                uint32_t A0[4], A1[4], B0[4], B1[4];
                ldsm_x4(A0, aV + 32 * u);
                ldsm_x4(A1, aV + 32 * u + 32 * SPV);
                ldsm_x4(B0, aP + 32 * u);
                ldsm_x4(B1, aP + 32 * u + 32 * SPV);
                mma16(oacc[0][0], A0, B0[0], B0[2]);
                mma16(oacc[1][0], A1, B0[0], B0[2]);
                mma16(oacc[0][1], A0, B0[1], B0[3]);
                mma16(oacc[1][1], A1, B0[1], B0[3]);
                mma16(oacc[0][2], A0, B1[0], B1[2]);
                mma16(oacc[1][2], A1, B1[0], B1[2]);
                mma16(oacc[0][3], A0, B1[1], B1[3]);
                mma16(oacc[1][3], A1, B1[1], B1[3]);

                if (hasN1) {
                    *(__half2*)&KhN[nk * SQK + chg * 16 + 2 * u] =
                        __floats2half2_rn(kx0, kx1);
                    kx0 = nx0; kx1 = nx1;
                }
            }
        }
    }

    // ---- finalize: row sums -> inv, normalize + store O^T ----
    __syncthreads();
    if (tig == 0) {
        float* rs = sm + ORA + wn * 128;
        const int mb = wm * 32;
        rs[mb + g]      = rsum[0];
        rs[mb + g + 8]  = rsum[1];
        rs[mb + g + 16] = rsum[2];
        rs[mb + g + 24] = rsum[3];
    }
    __syncthreads();
    if (t < 128)
        sm[OINV + t] = 1.0f / (sm[ORA + t] + sm[ORA + 128 + t] +
                               sm[ORA + 256 + t] + sm[ORA + 384 + t]);
    __syncthreads();

    {
        const int cb = wm * 32, mb2 = wn * 32;
#pragma unroll
        for (int i = 0; i < 2; i++)
#pragma unroll
            for (int f = 0; f < 4; f++) {
                int m_ = mb2 + 8 * f + 2 * tig;
                float iv0 = sm[OINV + m_], iv1 = sm[OINV + m_ + 1];
                int cv = cb + 16 * i + g;
                float* o0 = out + ((size_t)b * CVD + cv0 + cv) * MQ + m0 + m_;
                float* o1 = o0 + (size_t)8 * MQ;
                *(float2*)o0 = make_float2(oacc[i][f][0] * iv0, oacc[i][f][1] * iv1);
                *(float2*)o1 = make_float2(oacc[i][f][2] * iv0, oacc[i][f][3] * iv1);
            }
    }
}

// ---------------------------------------------------------------------------
extern "C" void kernel_launch(void* const* d_in, const int* in_sizes, int n_in,
                              void* d_out, int out_size) {
    const float* mk = (const float*)d_in[0];
    const float* qk = (const float*)d_in[1];
    const float* mv = (const float*)d_in[2];
    float* out = (float*)d_out;

    cudaFuncSetAttribute(mr_kernel, cudaFuncAttributeMaxDynamicSharedMemorySize,
                         SMEM_BYTES);
    dim3 grid(MQ / 128, CVD / 128, BATCH);   // 18 x 4 x 4 = 288
    mr_kernel<<<grid, THREADS, SMEM_BYTES>>>(mk, qk, mv, out);
}